// round 4
// baseline (speedup 1.0000x reference)
#include <cuda_runtime.h>
#include <cstdint>

#define SEQ 512
#define BATCH 64
#define IDIM 1024
#define HDIM 1024
#define G3 3072
#define CHUNK 64     // timesteps of gx precomputed per chunk
#define NCTA 128     // persistent grid size (<=148 SMs -> co-resident)

// ---------------- scratch (static device globals: allowed) ----------------
__device__ float g_gx[(size_t)CHUNK * BATCH * G3]; // 50 MB: gx chunk
__device__ float g_h[BATCH * HDIM];                // current hidden state
__device__ float g_z[BATCH * HDIM];                // z gate
__device__ float g_rh[BATCH * HDIM];               // r .* h

// ---------------- software grid barrier ----------------
__device__ unsigned int g_bar_gen = 0;
__device__ unsigned int g_bar_cnt = 0;

__device__ __forceinline__ void grid_sync()
{
    __syncthreads();
    if (threadIdx.x == 0) {
        unsigned int gen = *(volatile unsigned int*)&g_bar_gen;
        __threadfence();
        if (atomicAdd(&g_bar_cnt, 1u) == (unsigned)NCTA - 1u) {
            g_bar_cnt = 0;
            __threadfence();
            *(volatile unsigned int*)&g_bar_gen = gen + 1u;
        } else {
            while (*(volatile unsigned int*)&g_bar_gen == gen) __nanosleep(64);
        }
        __threadfence();
    }
    __syncthreads();
}

// ---------------- gx GEMM: C[CHUNK*64,3072] = A @ W_ih^T + b ----------------
__global__ void __launch_bounds__(256) gemm_gx_kernel(
    const float* __restrict__ A, const float* __restrict__ W,
    const float* __restrict__ bias)
{
    __shared__ float As[16][132];
    __shared__ float Bs[16][68];

    const int bm = blockIdx.y * 128;
    const int bn = blockIdx.x * 64;
    const int tid = threadIdx.x;

    float acc[8][4];
#pragma unroll
    for (int i = 0; i < 8; i++)
#pragma unroll
        for (int j = 0; j < 4; j++) acc[i][j] = 0.f;

    const int tx = tid & 15;
    const int ty = tid >> 4;

    for (int k0 = 0; k0 < IDIM; k0 += 16) {
#pragma unroll
        for (int j = 0; j < 2; j++) {
            int lid = tid + j * 256;
            int row = lid >> 2;
            int kk  = (lid & 3) * 4;
            float4 v = *(const float4*)&A[(size_t)(bm + row) * IDIM + k0 + kk];
            As[kk + 0][row] = v.x; As[kk + 1][row] = v.y;
            As[kk + 2][row] = v.z; As[kk + 3][row] = v.w;
        }
        {
            int row = tid >> 2;
            int kk  = (tid & 3) * 4;
            float4 v = *(const float4*)&W[(size_t)(bn + row) * IDIM + k0 + kk];
            Bs[kk + 0][row] = v.x; Bs[kk + 1][row] = v.y;
            Bs[kk + 2][row] = v.z; Bs[kk + 3][row] = v.w;
        }
        __syncthreads();

#pragma unroll
        for (int kk = 0; kk < 16; kk++) {
            float4 a0 = *(const float4*)&As[kk][ty * 8];
            float4 a1 = *(const float4*)&As[kk][ty * 8 + 4];
            float4 b  = *(const float4*)&Bs[kk][tx * 4];
            float a[8] = {a0.x, a0.y, a0.z, a0.w, a1.x, a1.y, a1.z, a1.w};
            float bb[4] = {b.x, b.y, b.z, b.w};
#pragma unroll
            for (int i = 0; i < 8; i++)
#pragma unroll
                for (int j = 0; j < 4; j++) acc[i][j] += a[i] * bb[j];
        }
        __syncthreads();
    }

#pragma unroll
    for (int i = 0; i < 8; i++) {
        int m = bm + ty * 8 + i;
#pragma unroll
        for (int j = 0; j < 4; j++) {
            int n = bn + tx * 4 + j;
            g_gx[(size_t)m * G3 + n] = acc[i][j] + bias[n];
        }
    }
}

// ---------------- init h ----------------
__global__ void init_h_kernel(const float* __restrict__ h0)
{
    int i = blockIdx.x * blockDim.x + threadIdx.x;
    if (i < BATCH * HDIM) g_h[i] = h0[i];
}

// ---------------- persistent recurrence: CHUNK steps per launch ----------------
// smem: WA [1024][16] (k-major), WB [1024][8] (k-major), Hs [32][66]
#define SM_WA 0
#define SM_WB (16 * 1024)
#define SM_HS (24 * 1024)
#define SMEM_FLOATS (24 * 1024 + 32 * 66)

__global__ void __launch_bounds__(256, 1) recurrence_kernel(
    int c0, const float* __restrict__ Whh, const float* __restrict__ bhh,
    float* __restrict__ Y)
{
    extern __shared__ float smem[];
    float* WA = smem + SM_WA;
    float* WB = smem + SM_WB;
    float* Hs = smem + SM_HS;

    const int tid = threadIdx.x;
    const int bid = blockIdx.x;
    const int nbA = bid * 16;   // rz column base (0..2047)
    const int nbB = bid * 8;    // n  column base (0..1023)

    // ---- load weight slices once (k-major for conflict-free reads) ----
    for (int i = tid; i < 16 * 1024; i += 256) {
        int n = i >> 10, k = i & 1023;
        WA[k * 16 + n] = Whh[(size_t)(nbA + n) * HDIM + k];
    }
    for (int i = tid; i < 8 * 1024; i += 256) {
        int n = i >> 10, k = i & 1023;
        WB[k * 8 + n] = Whh[(size_t)(2048 + nbB + n) * HDIM + k];
    }

    const int b0  = (tid >> 3) * 2;   // 0..62
    const int n0A = (tid & 7) * 2;    // 0..14
    const int n0B = tid & 7;          // 0..7

    const float bA0 = bhh[nbA + n0A];
    const float bA1 = bhh[nbA + n0A + 1];
    const float bB  = bhh[2048 + nbB + n0B];
    const bool  is_r = (nbA < HDIM);

    __syncthreads();

    for (int tc = 0; tc < CHUNK; tc++) {
        const float* gx_t = &g_gx[(size_t)tc * BATCH * G3];

        // ======== phase A: r/z gates ========
        float a00 = 0.f, a01 = 0.f, a10 = 0.f, a11 = 0.f;
        for (int k0 = 0; k0 < HDIM; k0 += 32) {
#pragma unroll
            for (int j = 0; j < 2; j++) {
                int lid = tid + j * 256;
                int b = lid >> 3, kk = (lid & 7) * 4;
                float4 v = *(const float4*)&g_h[b * HDIM + k0 + kk];
                Hs[(kk + 0) * 66 + b] = v.x; Hs[(kk + 1) * 66 + b] = v.y;
                Hs[(kk + 2) * 66 + b] = v.z; Hs[(kk + 3) * 66 + b] = v.w;
            }
            __syncthreads();
#pragma unroll
            for (int kk = 0; kk < 32; kk++) {
                float2 h2 = *(const float2*)&Hs[kk * 66 + b0];
                float2 w2 = *(const float2*)&WA[(k0 + kk) * 16 + n0A];
                a00 += h2.x * w2.x; a01 += h2.x * w2.y;
                a10 += h2.y * w2.x; a11 += h2.y * w2.y;
            }
            __syncthreads();
        }
        {
            int n = nbA + n0A;
            float v00 = gx_t[(b0 + 0) * G3 + n]     + bA0 + a00;
            float v01 = gx_t[(b0 + 0) * G3 + n + 1] + bA1 + a01;
            float v10 = gx_t[(b0 + 1) * G3 + n]     + bA0 + a10;
            float v11 = gx_t[(b0 + 1) * G3 + n + 1] + bA1 + a11;
            float s00 = 1.f / (1.f + __expf(-v00));
            float s01 = 1.f / (1.f + __expf(-v01));
            float s10 = 1.f / (1.f + __expf(-v10));
            float s11 = 1.f / (1.f + __expf(-v11));
            if (is_r) {
                g_rh[(b0 + 0) * HDIM + n]     = s00 * g_h[(b0 + 0) * HDIM + n];
                g_rh[(b0 + 0) * HDIM + n + 1] = s01 * g_h[(b0 + 0) * HDIM + n + 1];
                g_rh[(b0 + 1) * HDIM + n]     = s10 * g_h[(b0 + 1) * HDIM + n];
                g_rh[(b0 + 1) * HDIM + n + 1] = s11 * g_h[(b0 + 1) * HDIM + n + 1];
            } else {
                int nz = n - HDIM;
                g_z[(b0 + 0) * HDIM + nz]     = s00;
                g_z[(b0 + 0) * HDIM + nz + 1] = s01;
                g_z[(b0 + 1) * HDIM + nz]     = s10;
                g_z[(b0 + 1) * HDIM + nz + 1] = s11;
            }
        }
        grid_sync();

        // ======== phase B: n gate + state update ========
        float c0a = 0.f, c1a = 0.f;
        for (int k0 = 0; k0 < HDIM; k0 += 32) {
#pragma unroll
            for (int j = 0; j < 2; j++) {
                int lid = tid + j * 256;
                int b = lid >> 3, kk = (lid & 7) * 4;
                float4 v = *(const float4*)&g_rh[b * HDIM + k0 + kk];
                Hs[(kk + 0) * 66 + b] = v.x; Hs[(kk + 1) * 66 + b] = v.y;
                Hs[(kk + 2) * 66 + b] = v.z; Hs[(kk + 3) * 66 + b] = v.w;
            }
            __syncthreads();
#pragma unroll
            for (int kk = 0; kk < 32; kk++) {
                float2 h2 = *(const float2*)&Hs[kk * 66 + b0];
                float  w  = WB[(k0 + kk) * 8 + n0B];
                c0a += h2.x * w;
                c1a += h2.y * w;
            }
            __syncthreads();
        }
        {
            int n = nbB + n0B;
            int t = c0 + tc;
#pragma unroll
            for (int i = 0; i < 2; i++) {
                int b = b0 + i;
                float acc = (i == 0) ? c0a : c1a;
                float x = gx_t[b * G3 + 2048 + n] + bB + acc;
                // tanh(x) = 2*sigmoid(2x) - 1 (fast exp)
                float nv = 2.f / (1.f + __expf(-2.f * x)) - 1.f;
                float z  = g_z[b * HDIM + n];
                float ho = g_h[b * HDIM + n];
                float hn = (1.f - z) * nv + z * ho;
                g_h[b * HDIM + n] = hn;
                Y[((size_t)t * BATCH + b) * HDIM + n] = hn;
            }
        }
        grid_sync();
    }
}

// ---------------- write Y_h ----------------
__global__ void write_yh_kernel(float* __restrict__ out_tail)
{
    int i = blockIdx.x * blockDim.x + threadIdx.x;
    if (i < BATCH * HDIM) out_tail[i] = g_h[i];
}

// ---------------- launch ----------------
extern "C" void kernel_launch(void* const* d_in, const int* in_sizes, int n_in,
                              void* d_out, int out_size)
{
    const float* input  = (const float*)d_in[0];   // [512,64,1024]
    const float* h0     = (const float*)d_in[1];   // [1,64,1024]
    const float* w_ih   = (const float*)d_in[2];   // [3072,1024]
    const float* w_hh   = (const float*)d_in[3];   // [3072,1024]
    const float* b_ih   = (const float*)d_in[4];   // [3072]
    const float* b_hh   = (const float*)d_in[5];   // [3072]
    float* out = (float*)d_out;                    // Y then Y_h

    const int smem_bytes = SMEM_FLOATS * sizeof(float);  // ~106.7 KB
    cudaFuncSetAttribute(recurrence_kernel,
                         cudaFuncAttributeMaxDynamicSharedMemorySize, smem_bytes);

    init_h_kernel<<<(BATCH * HDIM + 255) / 256, 256>>>(h0);

    for (int c0 = 0; c0 < SEQ; c0 += CHUNK) {
        dim3 grid(G3 / 64, (CHUNK * BATCH) / 128);
        gemm_gx_kernel<<<grid, 256>>>(input + (size_t)c0 * BATCH * IDIM, w_ih, b_ih);
        recurrence_kernel<<<NCTA, 256, smem_bytes>>>(c0, w_hh, b_hh, out);
    }

    write_yh_kernel<<<(BATCH * HDIM + 255) / 256, 256>>>(out + (size_t)SEQ * BATCH * HDIM);
}